// round 13
// baseline (speedup 1.0000x reference)
#include <cuda_runtime.h>
#include <cuda_bf16.h>

// Problem constants
#define BATCH 8
#define CH    128
#define NPIX  2304     // 48*48
#define RED   16
#define NIT   36       // NPIX/64 i-tiles
#define NJS   72       // NPIX/32 j-steps

typedef unsigned long long u64;
typedef unsigned u32;

// ---------------- scratch (device globals; no allocation) --------------------
__device__ __align__(16) __nv_bfloat16 g_qh[(size_t)BATCH * NPIX * CH]; // [b][n][c]
__device__ __align__(16) __nv_bfloat16 g_ql[(size_t)BATCH * NPIX * CH];
__device__ __align__(16) __nv_bfloat16 g_kh[(size_t)BATCH * NPIX * CH]; // [b][n][c]
__device__ __align__(16) __nv_bfloat16 g_kl[(size_t)BATCH * NPIX * CH];
__device__ __align__(16) __nv_bfloat16 g_vh[(size_t)BATCH * CH * NPIX]; // [b][c][j]
__device__ __align__(16) __nv_bfloat16 g_vl[(size_t)BATCH * CH * NPIX];
__device__ float g_mean[BATCH * CH];
__device__ float g_se[BATCH * CH];

// ---------------- f32x2 packed-math helpers (qkv) ----------------------------
__device__ __forceinline__ u64 pack_dup(float a) {
    u64 r; asm("mov.b64 %0, {%1, %1};" : "=l"(r) : "f"(a)); return r;
}
__device__ __forceinline__ void unpack2(u64 v, float& lo, float& hi) {
    asm("mov.b64 {%0, %1}, %2;" : "=f"(lo), "=f"(hi) : "l"(v));
}
__device__ __forceinline__ void ffma2(u64& d, u64 a, u64 b) {
    asm("fma.rn.f32x2 %0, %1, %2, %3;" : "=l"(d) : "l"(a), "l"(b), "l"(d));
}

// ---------------- HMMA / cp.async helpers ------------------------------------
__device__ __forceinline__ void ldm4(u32* r, u32 a) {
    asm volatile("ldmatrix.sync.aligned.m8n8.x4.shared.b16 {%0,%1,%2,%3}, [%4];"
        : "=r"(r[0]), "=r"(r[1]), "=r"(r[2]), "=r"(r[3]) : "r"(a));
}
__device__ __forceinline__ void mma_bf16(float* c, const u32* a, const u32* b) {
    asm volatile("mma.sync.aligned.m16n8k16.row.col.f32.bf16.bf16.f32 "
        "{%0,%1,%2,%3}, {%4,%5,%6,%7}, {%8,%9}, {%0,%1,%2,%3};"
        : "+f"(c[0]), "+f"(c[1]), "+f"(c[2]), "+f"(c[3])
        : "r"(a[0]), "r"(a[1]), "r"(a[2]), "r"(a[3]), "r"(b[0]), "r"(b[1]));
}
#define CP16(dst, src) \
    asm volatile("cp.async.cg.shared.global [%0], [%1], 16;" :: "r"(dst), "l"(src))
#define CPCOMMIT() asm volatile("cp.async.commit_group;" ::: "memory")
#define CPWAIT(n)  asm volatile("cp.async.wait_group %0;" :: "n"(n) : "memory")

// q tile: 64 rows x 128 bf16 (256B), stride 272B.  k tile: 32 rows x 128 bf16,
// stride 272B.  v tile: 128 rows x 32 bf16 (64B), stride 80B (odd*16B).
#define RSQK 272
#define RSV  80
#define TQ   (64 * RSQK)           // 17408 B
#define TK   (32 * RSQK)           //  8704 B
#define TV   (128 * RSV)           // 10240 B
#define O_QH 0
#define O_QL (O_QH + TQ)
#define O_KH (O_QL + TQ)
#define O_KL (O_KH + TK)
#define O_VH (O_KL + TK)
#define O_VL (O_VH + TV)
#define O_RS (O_VL + TV)           // float[64] rowsums
#define SMEM_F (O_RS + 256)        // 72960 B -> 3 CTAs/SM

__device__ __forceinline__ u32 packbf2(float a, float b) {
    __nv_bfloat162 t = __floats2bfloat162_rn(a, b);
    return *(u32*)&t;
}

__device__ __forceinline__ void split4_store(__nv_bfloat16* ph, __nv_bfloat16* pl,
                                             size_t idx, float a, float b,
                                             float c, float d) {
    __nv_bfloat16 h0 = __float2bfloat16(a), h1 = __float2bfloat16(b);
    __nv_bfloat16 h2 = __float2bfloat16(c), h3 = __float2bfloat16(d);
    float l0 = a - __bfloat162float(h0), l1 = b - __bfloat162float(h1);
    float l2 = c - __bfloat162float(h2), l3 = d - __bfloat162float(h3);
    uint2 hp, lp;
    hp.x = (u32)__bfloat16_as_ushort(h0) | ((u32)__bfloat16_as_ushort(h1) << 16);
    hp.y = (u32)__bfloat16_as_ushort(h2) | ((u32)__bfloat16_as_ushort(h3) << 16);
    lp.x = packbf2(l0, l1);
    lp.y = packbf2(l2, l3);
    *(uint2*)(ph + idx) = hp;
    *(uint2*)(pl + idx) = lp;
}

// Copy 64 rows x 256B (q plane), 128 threads.
__device__ __forceinline__ void cp_q(u32 dst, const char* src, int tid) {
#pragma unroll
    for (int rep = 0; rep < 8; rep++) {
        int id = rep * 128 + tid;
        int row = id >> 4, ch = (id & 15) << 4;
        CP16(dst + row * RSQK + ch, src + row * 256 + ch);
    }
}
// Copy 32 rows x 256B (k plane), 128 threads.
__device__ __forceinline__ void cp_k(u32 dst, const char* src, int tid) {
#pragma unroll
    for (int rep = 0; rep < 4; rep++) {
        int id = rep * 128 + tid;
        int row = id >> 4, ch = (id & 15) << 4;
        CP16(dst + row * RSQK + ch, src + row * 256 + ch);
    }
}
// Copy 128 rows x 64B (v plane, global row stride 4608B), 128 threads.
__device__ __forceinline__ void cp_v(u32 dst, const char* src, int tid) {
#pragma unroll
    for (int rep = 0; rep < 4; rep++) {
        int id = rep * 128 + tid;
        int row = id >> 2, ch = (id & 3) << 4;
        CP16(dst + row * RSV + ch, src + (size_t)row * 4608 + ch);
    }
}

// =============================================================================
// Kernel 1: QKV. Emits pre-split bf16 planes: q,k [b][n][c], v [b][c][j].
// =============================================================================
__global__ __launch_bounds__(256) void qkv_kernel(
    const float* __restrict__ x,
    const float* __restrict__ Wq, const float* __restrict__ bq,
    const float* __restrict__ Wk, const float* __restrict__ bk,
    const float* __restrict__ Wv, const float* __restrict__ bv)
{
    __shared__ __align__(16) float xs[CH * 64];
    const int n0 = blockIdx.x * 64;
    const int b  = blockIdx.y;
    const int m  = blockIdx.z;
    const float* W    = (m == 0) ? Wq : ((m == 1) ? Wk : Wv);
    const float* bias = (m == 0) ? bq : ((m == 1) ? bk : bv);

    const int t = threadIdx.x;
    for (int idx = t; idx < CH * 64; idx += 256) {
        int ci = idx >> 6, nn = idx & 63;
        xs[idx] = x[(size_t)(b * CH + ci) * NPIX + n0 + nn];
    }
    __syncthreads();

    const int co0 = (t >> 3) << 2;
    const int nn0 = (t & 7) << 3;

    u64 acc[4][4];
#pragma unroll
    for (int u = 0; u < 4; u++)
#pragma unroll
        for (int v = 0; v < 4; v++) acc[u][v] = 0ull;

#pragma unroll 1
    for (int ci0 = 0; ci0 < CH; ci0 += 4) {
        float wr[4][4];
#pragma unroll
        for (int u = 0; u < 4; u++) {
            float4 f = *(const float4*)&W[(co0 + u) * CH + ci0];
            wr[u][0] = f.x; wr[u][1] = f.y; wr[u][2] = f.z; wr[u][3] = f.w;
        }
#pragma unroll
        for (int kk = 0; kk < 4; kk++) {
            const u64* xp = (const u64*)&xs[(ci0 + kk) * 64 + nn0];
            u64 x0 = xp[0], x1 = xp[1], x2 = xp[2], x3 = xp[3];
#pragma unroll
            for (int u = 0; u < 4; u++) {
                u64 a2 = pack_dup(wr[u][kk]);
                ffma2(acc[u][0], a2, x0);
                ffma2(acc[u][1], a2, x1);
                ffma2(acc[u][2], a2, x2);
                ffma2(acc[u][3], a2, x3);
            }
        }
    }

    float bs[4];
#pragma unroll
    for (int u = 0; u < 4; u++) bs[u] = bias[co0 + u];

    if (m == 2) {  // v: [b][c][j]
#pragma unroll
        for (int u = 0; u < 4; u++) {
            size_t base = (size_t)(b * CH + co0 + u) * NPIX + n0 + nn0;
            float f[8];
#pragma unroll
            for (int v = 0; v < 4; v++) {
                unpack2(acc[u][v], f[2 * v], f[2 * v + 1]);
                f[2 * v] += bs[u]; f[2 * v + 1] += bs[u];
            }
            split4_store(g_vh, g_vl, base,     f[0], f[1], f[2], f[3]);
            split4_store(g_vh, g_vl, base + 4, f[4], f[5], f[6], f[7]);
        }
    } else {       // q,k: [b][n][c]
        __nv_bfloat16* ph = (m == 0) ? g_qh : g_kh;
        __nv_bfloat16* pl = (m == 0) ? g_ql : g_kl;
#pragma unroll
        for (int v = 0; v < 4; v++) {
            float o0[4], o1[4];
#pragma unroll
            for (int u = 0; u < 4; u++) {
                unpack2(acc[u][v], o0[u], o1[u]);
                o0[u] += bs[u]; o1[u] += bs[u];
            }
            int n = n0 + nn0 + 2 * v;
            split4_store(ph, pl, ((size_t)b * NPIX + n) * CH + co0,
                         o0[0], o0[1], o0[2], o0[3]);
            split4_store(ph, pl, ((size_t)b * NPIX + n + 1) * CH + co0,
                         o1[0], o1[1], o1[2], o1[3]);
        }
    }
}

// =============================================================================
// Kernel 2a/2b: SE path (unchanged)
// =============================================================================
__global__ __launch_bounds__(256) void mean_kernel(const float* __restrict__ x)
{
    const int row = blockIdx.x;
    const float* p = x + (size_t)row * NPIX;
    const int t = threadIdx.x;
    float s = 0.f;
#pragma unroll
    for (int k = 0; k < 9; k++) s += p[t + k * 256];
#pragma unroll
    for (int o = 16; o > 0; o >>= 1) s += __shfl_xor_sync(0xffffffffu, s, o);
    __shared__ float red[8];
    if ((t & 31) == 0) red[t >> 5] = s;
    __syncthreads();
    if (t == 0) {
        float tot = red[0];
#pragma unroll
        for (int r = 1; r < 8; r++) tot += red[r];
        g_mean[row] = tot * (1.0f / (float)NPIX);
    }
}

__global__ __launch_bounds__(128) void se_kernel(
    const float* __restrict__ w1, const float* __restrict__ w2)
{
    __shared__ float hid[BATCH * (CH / RED)];
    const int t = threadIdx.x;
    if (t < 64) {
        int b = t >> 3, h = t & 7;
        float s = 0.f;
#pragma unroll 4
        for (int c = 0; c < CH; c++) s += g_mean[b * CH + c] * w1[h * CH + c];
        hid[t] = fmaxf(s, 0.f);
    }
    __syncthreads();
    for (int idx = t; idx < BATCH * CH; idx += 128) {
        int b = idx >> 7, c = idx & 127;
        float s = 0.f;
#pragma unroll
        for (int h = 0; h < 8; h++) s += hid[b * 8 + h] * w2[c * 8 + h];
        g_se[idx] = 1.0f / (1.0f + __expf(-s));
    }
}

// =============================================================================
// Kernel 3: fused attention, 3-CTAs/SM variant.
// CTA = 128 threads / 4 warps, i-tile 64 (warp owns 16 rows), j-steps of 32.
// S = q.kT (3-term split), p = exp(S) in regs, out += p.vT (3 terms).
// exp phase runs BEFORE the k-barrier (register-only, overlaps v cp.async).
// =============================================================================
__global__ __launch_bounds__(128, 3) void fused_attn(
    const float* __restrict__ x, const float* __restrict__ gamma,
    float* __restrict__ outp)
{
    extern __shared__ __align__(16) char sm[];
    const u32 sb = (u32)__cvta_generic_to_shared(sm);
    const int tid = threadIdx.x, warp = tid >> 5, lane = tid & 31;
    const int i0 = blockIdx.x * 64, b = blockIdx.y;

    const char* qh = (const char*)(g_qh + ((size_t)b * NPIX + i0) * CH);
    const char* ql = (const char*)(g_ql + ((size_t)b * NPIX + i0) * CH);
    const char* kh = (const char*)(g_kh + (size_t)b * NPIX * CH);
    const char* kl = (const char*)(g_kl + (size_t)b * NPIX * CH);
    const char* vh = (const char*)(g_vh + (size_t)b * CH * NPIX);
    const char* vl = (const char*)(g_vl + (size_t)b * CH * NPIX);

    // prologue: q, k(0), v(0)
    cp_q(sb + O_QH, qh, tid);
    cp_q(sb + O_QL, ql, tid);
    CPCOMMIT();
    cp_k(sb + O_KH, kh, tid);
    cp_k(sb + O_KL, kl, tid);
    CPCOMMIT();
    cp_v(sb + O_VH, vh, tid);
    cp_v(sb + O_VL, vl, tid);
    CPCOMMIT();
    CPWAIT(1);
    __syncthreads();

    // ldmatrix bases
    const u32 aQ = sb + O_QH + (u32)((warp * 16 + (lane & 15)) * RSQK
                                     + ((lane >> 4) << 4));
    const u32 bK = sb + O_KH + (u32)(((((lane >> 4) & 1) << 3) + (lane & 7)) * RSQK
                                     + (((lane >> 3) & 1) << 4));
    const u32 bV = sb + O_VH + (u32)(((((lane >> 4) & 1) << 3) + (lane & 7)) * RSV
                                     + (((lane >> 3) & 1) << 4));

    float accO[16][4];
#pragma unroll
    for (int nt = 0; nt < 16; nt++)
#pragma unroll
        for (int q = 0; q < 4; q++) accO[nt][q] = 0.f;
    float rs0 = 0.f, rs1 = 0.f;

#pragma unroll 1
    for (int jt = 0; jt < NJS; jt++) {
        // ---- S = q . k^T  (M=16/warp, N=32, K=128) ----
        float accS[4][4];
#pragma unroll
        for (int nt = 0; nt < 4; nt++)
#pragma unroll
            for (int q = 0; q < 4; q++) accS[nt][q] = 0.f;
#pragma unroll
        for (int ks = 0; ks < 8; ks++) {
            u32 ah[4], al[4];
            ldm4(ah, aQ + ks * 32);
            ldm4(al, aQ + ks * 32 + TQ);
#pragma unroll
            for (int np = 0; np < 2; np++) {
                u32 bh[4], bl[4];
                ldm4(bh, bK + np * (16 * RSQK) + ks * 32);
                ldm4(bl, bK + np * (16 * RSQK) + ks * 32 + TK);
                mma_bf16(accS[2 * np],     ah, bh);
                mma_bf16(accS[2 * np],     al, bh);
                mma_bf16(accS[2 * np],     ah, bl);
                mma_bf16(accS[2 * np + 1], ah, bh + 2);
                mma_bf16(accS[2 * np + 1], al, bh + 2);
                mma_bf16(accS[2 * np + 1], ah, bl + 2);
            }
        }

        // ---- p = exp(S) repacked into A fragments (register-only) ----
        u32 pa[2][4], pb[2][4];
#pragma unroll
        for (int ks = 0; ks < 2; ks++) {
#pragma unroll
            for (int h = 0; h < 2; h++) {
                const int nt = 2 * ks + h;
                float e0 = __expf(accS[nt][0]);
                float e1 = __expf(accS[nt][1]);
                float e2 = __expf(accS[nt][2]);
                float e3 = __expf(accS[nt][3]);
                rs0 += e0 + e1; rs1 += e2 + e3;
                __nv_bfloat16 h0 = __float2bfloat16(e0), h1 = __float2bfloat16(e1);
                __nv_bfloat16 h2 = __float2bfloat16(e2), h3 = __float2bfloat16(e3);
                pa[ks][2 * h]     = (u32)__bfloat16_as_ushort(h0)
                                  | ((u32)__bfloat16_as_ushort(h1) << 16);
                pa[ks][2 * h + 1] = (u32)__bfloat16_as_ushort(h2)
                                  | ((u32)__bfloat16_as_ushort(h3) << 16);
                pb[ks][2 * h]     = packbf2(e0 - __bfloat162float(h0),
                                            e1 - __bfloat162float(h1));
                pb[ks][2 * h + 1] = packbf2(e2 - __bfloat162float(h2),
                                            e3 - __bfloat162float(h3));
            }
        }

        CPWAIT(0);          // v(jt) arrived
        __syncthreads();    // all warps past k(jt) reads
        if (jt + 1 < NJS) {
            cp_k(sb + O_KH, kh + (size_t)(jt + 1) * 32 * 256, tid);
            cp_k(sb + O_KL, kl + (size_t)(jt + 1) * 32 * 256, tid);
            CPCOMMIT();
        }

        // ---- out += p . v^T  (M=16, N=128 c, K=32 j) ----
#pragma unroll
        for (int ks = 0; ks < 2; ks++) {
#pragma unroll
            for (int np = 0; np < 8; np++) {
                u32 wh[4], wl[4];
                ldm4(wh, bV + np * (16 * RSV) + ks * 32);
                ldm4(wl, bV + np * (16 * RSV) + ks * 32 + TV);
                mma_bf16(accO[2 * np],     pa[ks], wh);
                mma_bf16(accO[2 * np],     pb[ks], wh);
                mma_bf16(accO[2 * np],     pa[ks], wl);
                mma_bf16(accO[2 * np + 1], pa[ks], wh + 2);
                mma_bf16(accO[2 * np + 1], pb[ks], wh + 2);
                mma_bf16(accO[2 * np + 1], pa[ks], wl + 2);
            }
        }
        CPWAIT(0);          // k(jt+1) arrived
        __syncthreads();    // v buffer free
        if (jt + 1 < NJS) {
            cp_v(sb + O_VH, vh + (size_t)(jt + 1) * 64, tid);
            cp_v(sb + O_VL, vl + (size_t)(jt + 1) * 64, tid);
            CPCOMMIT();
        }
    }

    // ---- rowsum reduce (quad shuffle) + transpose accO into q region ----
    float* rssm = (float*)(sm + O_RS);
    rs0 += __shfl_xor_sync(0xffffffffu, rs0, 1);
    rs0 += __shfl_xor_sync(0xffffffffu, rs0, 2);
    rs1 += __shfl_xor_sync(0xffffffffu, rs1, 1);
    rs1 += __shfl_xor_sync(0xffffffffu, rs1, 2);
    if ((lane & 3) == 0) {
        rssm[warp * 16 + (lane >> 2)]     = rs0;
        rssm[warp * 16 + 8 + (lane >> 2)] = rs1;
    }

    float* trans = (float*)sm;   // 128 c x 68 stride floats = 34816 B (q region)
    {
        const int r = lane >> 2, c0 = 2 * (lane & 3);
        const int iA = warp * 16 + r, iB = iA + 8;
#pragma unroll
        for (int nt = 0; nt < 16; nt++) {
            const int c = nt * 8 + c0;
            trans[c * 68 + iA]       = accO[nt][0];
            trans[(c + 1) * 68 + iA] = accO[nt][1];
            trans[c * 68 + iB]       = accO[nt][2];
            trans[(c + 1) * 68 + iB] = accO[nt][3];
        }
    }
    __syncthreads();

    // ---- coalesced epilogue: /rowsum *gamma + x*se (half-warp per c-row) ----
    const float gam = gamma[0];
    const int ic = (lane & 15) * 4;
    float4 rsv = *(float4*)&rssm[ic];
    const float4 ri = make_float4(1.f / rsv.x, 1.f / rsv.y, 1.f / rsv.z, 1.f / rsv.w);
#pragma unroll
    for (int rp = 0; rp < 16; rp++) {
        const int c = warp * 32 + 2 * rp + (lane >> 4);
        const float sec = g_se[b * CH + c];
        const size_t base = (size_t)(b * CH + c) * NPIX + i0 + ic;
        float4 tv = *(float4*)&trans[c * 68 + ic];
        float4 xv = *(const float4*)&x[base];
        float4 o;
        o.x = gam * (tv.x * ri.x) + xv.x * sec;
        o.y = gam * (tv.y * ri.y) + xv.y * sec;
        o.z = gam * (tv.z * ri.z) + xv.z * sec;
        o.w = gam * (tv.w * ri.w) + xv.w * sec;
        *(float4*)&outp[base] = o;
    }
}

// =============================================================================
extern "C" void kernel_launch(void* const* d_in, const int* in_sizes, int n_in,
                              void* d_out, int out_size)
{
    const float* x     = (const float*)d_in[0];
    const float* Wq    = (const float*)d_in[1];
    const float* bq    = (const float*)d_in[2];
    const float* Wk    = (const float*)d_in[3];
    const float* bk    = (const float*)d_in[4];
    const float* Wv    = (const float*)d_in[5];
    const float* bv    = (const float*)d_in[6];
    const float* w1    = (const float*)d_in[7];
    const float* w2    = (const float*)d_in[8];
    const float* gamma = (const float*)d_in[9];
    float* out = (float*)d_out;

    cudaFuncSetAttribute(fused_attn, cudaFuncAttributeMaxDynamicSharedMemorySize,
                         SMEM_F);

    qkv_kernel<<<dim3(NPIX / 64, BATCH, 3), 256>>>(x, Wq, bq, Wk, bk, Wv, bv);
    mean_kernel<<<BATCH * CH, 256>>>(x);
    se_kernel<<<1, 128>>>(w1, w2);
    fused_attn<<<dim3(NIT, BATCH), 128, SMEM_F>>>(x, gamma, out);
}

// round 14
// speedup vs baseline: 1.0247x; 1.0247x over previous
#include <cuda_runtime.h>
#include <cuda_bf16.h>

// Problem constants
#define BATCH 8
#define CH    128
#define NPIX  2304     // 48*48
#define RED   16
#define NIT   18       // NPIX/128 i-tiles
#define NJS   36       // NPIX/64 j-steps

typedef unsigned long long u64;
typedef unsigned u32;

// ---------------- scratch (device globals; no allocation) --------------------
__device__ __align__(16) __nv_bfloat16 g_qh[(size_t)BATCH * NPIX * CH]; // [b][n][c]
__device__ __align__(16) __nv_bfloat16 g_ql[(size_t)BATCH * NPIX * CH];
__device__ __align__(16) __nv_bfloat16 g_kh[(size_t)BATCH * NPIX * CH]; // [b][n][c]
__device__ __align__(16) __nv_bfloat16 g_kl[(size_t)BATCH * NPIX * CH];
__device__ __align__(16) __nv_bfloat16 g_vh[(size_t)BATCH * CH * NPIX]; // [b][c][j]
__device__ __align__(16) __nv_bfloat16 g_vl[(size_t)BATCH * CH * NPIX];
__device__ float g_mean[BATCH * CH];
__device__ float g_se[BATCH * CH];

// ---------------- f32x2 packed-math helpers (qkv) ----------------------------
__device__ __forceinline__ u64 pack_dup(float a) {
    u64 r; asm("mov.b64 %0, {%1, %1};" : "=l"(r) : "f"(a)); return r;
}
__device__ __forceinline__ void unpack2(u64 v, float& lo, float& hi) {
    asm("mov.b64 {%0, %1}, %2;" : "=f"(lo), "=f"(hi) : "l"(v));
}
__device__ __forceinline__ void ffma2(u64& d, u64 a, u64 b) {
    asm("fma.rn.f32x2 %0, %1, %2, %3;" : "=l"(d) : "l"(a), "l"(b), "l"(d));
}

// ---------------- HMMA / cp.async helpers ------------------------------------
__device__ __forceinline__ void ldm4(u32* r, u32 a) {
    asm volatile("ldmatrix.sync.aligned.m8n8.x4.shared.b16 {%0,%1,%2,%3}, [%4];"
        : "=r"(r[0]), "=r"(r[1]), "=r"(r[2]), "=r"(r[3]) : "r"(a));
}
__device__ __forceinline__ void mma_bf16(float* c, const u32* a, const u32* b) {
    asm volatile("mma.sync.aligned.m16n8k16.row.col.f32.bf16.bf16.f32 "
        "{%0,%1,%2,%3}, {%4,%5,%6,%7}, {%8,%9}, {%0,%1,%2,%3};"
        : "+f"(c[0]), "+f"(c[1]), "+f"(c[2]), "+f"(c[3])
        : "r"(a[0]), "r"(a[1]), "r"(a[2]), "r"(a[3]), "r"(b[0]), "r"(b[1]));
}
#define CP16(dst, src) \
    asm volatile("cp.async.cg.shared.global [%0], [%1], 16;" :: "r"(dst), "l"(src))
#define CPCOMMIT() asm volatile("cp.async.commit_group;" ::: "memory")
#define CPWAIT(n)  asm volatile("cp.async.wait_group %0;" :: "n"(n) : "memory")

// q tile: 128 rows x 128c bf16 (256B), stride 272B.
// k tile:  64 rows x 128c bf16 (256B), stride 272B, DOUBLE buffered.
// v tile: 128 rows x  64j bf16 (128B), stride 144B, DOUBLE buffered.
#define RSQK 272
#define RSV  144
#define TQ   (128 * RSQK)          // 34816 B per plane
#define TK   (64 * RSQK)           // 17408 B per plane
#define TV   (128 * RSV)           // 18432 B per plane
#define O_QH  0
#define O_QL  (O_QH + TQ)          // q ends 69632
#define O_K0  (O_QL + TQ)          // buffer 0: hi, lo at +TK
#define O_K1  (O_K0 + 2 * TK)      // k ends 139264
#define O_V0  (O_K1 + 2 * TK)      // buffer 0: hi, lo at +TV
#define O_V1  (O_V0 + 2 * TV)
#define O_RS  (O_V1 + 2 * TV)      // 212992; float[128] rowsums
#define SMEM_F (O_RS + 512)        // 213504 B -> 1 CTA/SM

__device__ __forceinline__ u32 packbf2(float a, float b) {
    __nv_bfloat162 t = __floats2bfloat162_rn(a, b);
    return *(u32*)&t;
}

__device__ __forceinline__ void split4_store(__nv_bfloat16* ph, __nv_bfloat16* pl,
                                             size_t idx, float a, float b,
                                             float c, float d) {
    __nv_bfloat16 h0 = __float2bfloat16(a), h1 = __float2bfloat16(b);
    __nv_bfloat16 h2 = __float2bfloat16(c), h3 = __float2bfloat16(d);
    float l0 = a - __bfloat162float(h0), l1 = b - __bfloat162float(h1);
    float l2 = c - __bfloat162float(h2), l3 = d - __bfloat162float(h3);
    uint2 hp, lp;
    hp.x = (u32)__bfloat16_as_ushort(h0) | ((u32)__bfloat16_as_ushort(h1) << 16);
    hp.y = (u32)__bfloat16_as_ushort(h2) | ((u32)__bfloat16_as_ushort(h3) << 16);
    lp.x = packbf2(l0, l1);
    lp.y = packbf2(l2, l3);
    *(uint2*)(ph + idx) = hp;
    *(uint2*)(pl + idx) = lp;
}

// 256-thread copies.
__device__ __forceinline__ void cp_q(u32 dst, const char* src, int tid) {
#pragma unroll
    for (int rep = 0; rep < 8; rep++) {          // 128 rows x 16 chunks
        int id = rep * 256 + tid;
        int row = id >> 4, ch = (id & 15) << 4;
        CP16(dst + row * RSQK + ch, src + row * 256 + ch);
    }
}
__device__ __forceinline__ void cp_k(u32 dst, const char* src, int tid) {
#pragma unroll
    for (int rep = 0; rep < 4; rep++) {          // 64 rows x 16 chunks
        int id = rep * 256 + tid;
        int row = id >> 4, ch = (id & 15) << 4;
        CP16(dst + row * RSQK + ch, src + row * 256 + ch);
    }
}
__device__ __forceinline__ void cp_v(u32 dst, const char* src, int tid) {
#pragma unroll
    for (int rep = 0; rep < 4; rep++) {          // 128 rows x 8 chunks
        int id = rep * 256 + tid;
        int row = id >> 3, ch = (id & 7) << 4;
        CP16(dst + row * RSV + ch, src + (size_t)row * 4608 + ch);
    }
}

// =============================================================================
// Kernel 1: QKV. Emits pre-split bf16 planes: q,k [b][n][c], v [b][c][j].
// =============================================================================
__global__ __launch_bounds__(256) void qkv_kernel(
    const float* __restrict__ x,
    const float* __restrict__ Wq, const float* __restrict__ bq,
    const float* __restrict__ Wk, const float* __restrict__ bk,
    const float* __restrict__ Wv, const float* __restrict__ bv)
{
    __shared__ __align__(16) float xs[CH * 64];
    const int n0 = blockIdx.x * 64;
    const int b  = blockIdx.y;
    const int m  = blockIdx.z;
    const float* W    = (m == 0) ? Wq : ((m == 1) ? Wk : Wv);
    const float* bias = (m == 0) ? bq : ((m == 1) ? bk : bv);

    const int t = threadIdx.x;
    for (int idx = t; idx < CH * 64; idx += 256) {
        int ci = idx >> 6, nn = idx & 63;
        xs[idx] = x[(size_t)(b * CH + ci) * NPIX + n0 + nn];
    }
    __syncthreads();

    const int co0 = (t >> 3) << 2;
    const int nn0 = (t & 7) << 3;

    u64 acc[4][4];
#pragma unroll
    for (int u = 0; u < 4; u++)
#pragma unroll
        for (int v = 0; v < 4; v++) acc[u][v] = 0ull;

#pragma unroll 1
    for (int ci0 = 0; ci0 < CH; ci0 += 4) {
        float wr[4][4];
#pragma unroll
        for (int u = 0; u < 4; u++) {
            float4 f = *(const float4*)&W[(co0 + u) * CH + ci0];
            wr[u][0] = f.x; wr[u][1] = f.y; wr[u][2] = f.z; wr[u][3] = f.w;
        }
#pragma unroll
        for (int kk = 0; kk < 4; kk++) {
            const u64* xp = (const u64*)&xs[(ci0 + kk) * 64 + nn0];
            u64 x0 = xp[0], x1 = xp[1], x2 = xp[2], x3 = xp[3];
#pragma unroll
            for (int u = 0; u < 4; u++) {
                u64 a2 = pack_dup(wr[u][kk]);
                ffma2(acc[u][0], a2, x0);
                ffma2(acc[u][1], a2, x1);
                ffma2(acc[u][2], a2, x2);
                ffma2(acc[u][3], a2, x3);
            }
        }
    }

    float bs[4];
#pragma unroll
    for (int u = 0; u < 4; u++) bs[u] = bias[co0 + u];

    if (m == 2) {  // v: [b][c][j]
#pragma unroll
        for (int u = 0; u < 4; u++) {
            size_t base = (size_t)(b * CH + co0 + u) * NPIX + n0 + nn0;
            float f[8];
#pragma unroll
            for (int v = 0; v < 4; v++) {
                unpack2(acc[u][v], f[2 * v], f[2 * v + 1]);
                f[2 * v] += bs[u]; f[2 * v + 1] += bs[u];
            }
            split4_store(g_vh, g_vl, base,     f[0], f[1], f[2], f[3]);
            split4_store(g_vh, g_vl, base + 4, f[4], f[5], f[6], f[7]);
        }
    } else {       // q,k: [b][n][c]
        __nv_bfloat16* ph = (m == 0) ? g_qh : g_kh;
        __nv_bfloat16* pl = (m == 0) ? g_ql : g_kl;
#pragma unroll
        for (int v = 0; v < 4; v++) {
            float o0[4], o1[4];
#pragma unroll
            for (int u = 0; u < 4; u++) {
                unpack2(acc[u][v], o0[u], o1[u]);
                o0[u] += bs[u]; o1[u] += bs[u];
            }
            int n = n0 + nn0 + 2 * v;
            split4_store(ph, pl, ((size_t)b * NPIX + n) * CH + co0,
                         o0[0], o0[1], o0[2], o0[3]);
            split4_store(ph, pl, ((size_t)b * NPIX + n + 1) * CH + co0,
                         o1[0], o1[1], o1[2], o1[3]);
        }
    }
}

// =============================================================================
// Kernel 2a/2b: SE path (unchanged)
// =============================================================================
__global__ __launch_bounds__(256) void mean_kernel(const float* __restrict__ x)
{
    const int row = blockIdx.x;
    const float* p = x + (size_t)row * NPIX;
    const int t = threadIdx.x;
    float s = 0.f;
#pragma unroll
    for (int k = 0; k < 9; k++) s += p[t + k * 256];
#pragma unroll
    for (int o = 16; o > 0; o >>= 1) s += __shfl_xor_sync(0xffffffffu, s, o);
    __shared__ float red[8];
    if ((t & 31) == 0) red[t >> 5] = s;
    __syncthreads();
    if (t == 0) {
        float tot = red[0];
#pragma unroll
        for (int r = 1; r < 8; r++) tot += red[r];
        g_mean[row] = tot * (1.0f / (float)NPIX);
    }
}

__global__ __launch_bounds__(128) void se_kernel(
    const float* __restrict__ w1, const float* __restrict__ w2)
{
    __shared__ float hid[BATCH * (CH / RED)];
    const int t = threadIdx.x;
    if (t < 64) {
        int b = t >> 3, h = t & 7;
        float s = 0.f;
#pragma unroll 4
        for (int c = 0; c < CH; c++) s += g_mean[b * CH + c] * w1[h * CH + c];
        hid[t] = fmaxf(s, 0.f);
    }
    __syncthreads();
    for (int idx = t; idx < BATCH * CH; idx += 128) {
        int b = idx >> 7, c = idx & 127;
        float s = 0.f;
#pragma unroll
        for (int h = 0; h < 8; h++) s += hid[b * 8 + h] * w2[c * 8 + h];
        g_se[idx] = 1.0f / (1.0f + __expf(-s));
    }
}

// =============================================================================
// Kernel 3: fused attention, double-buffered k/v (jt+2 prefetch).
// 256 threads / 8 warps, i-tile 128 (warp owns 16 rows), j-steps of 64.
// S = q.kT (3-term split), p = exp(S) in regs, out += p.vT (3 terms).
// All waits/barriers at iteration boundary; copies get a full iteration.
// =============================================================================
__global__ __launch_bounds__(256) void fused_attn(
    const float* __restrict__ x, const float* __restrict__ gamma,
    float* __restrict__ outp)
{
    extern __shared__ __align__(16) char sm[];
    const u32 sb = (u32)__cvta_generic_to_shared(sm);
    const int tid = threadIdx.x, warp = tid >> 5, lane = tid & 31;
    const int i0 = blockIdx.x * 128, b = blockIdx.y;

    const char* qh = (const char*)(g_qh + ((size_t)b * NPIX + i0) * CH);
    const char* ql = (const char*)(g_ql + ((size_t)b * NPIX + i0) * CH);
    const char* kh = (const char*)(g_kh + (size_t)b * NPIX * CH);
    const char* kl = (const char*)(g_kl + (size_t)b * NPIX * CH);
    const char* vh = (const char*)(g_vh + (size_t)b * CH * NPIX);
    const char* vl = (const char*)(g_vl + (size_t)b * CH * NPIX);

    // prologue: q | k0,v0 (jt=0) | k1,v1 (jt=1)
    cp_q(sb + O_QH, qh, tid);
    cp_q(sb + O_QL, ql, tid);
    CPCOMMIT();
    cp_k(sb + O_K0,      kh, tid);
    cp_k(sb + O_K0 + TK, kl, tid);
    cp_v(sb + O_V0,      vh, tid);
    cp_v(sb + O_V0 + TV, vl, tid);
    CPCOMMIT();
    cp_k(sb + O_K1,      kh + 64 * 256, tid);
    cp_k(sb + O_K1 + TK, kl + 64 * 256, tid);
    cp_v(sb + O_V1,      vh + 128, tid);
    cp_v(sb + O_V1 + TV, vl + 128, tid);
    CPCOMMIT();
    CPWAIT(1);            // q + (k0,v0) done; (k1,v1) may be in flight
    __syncthreads();

    const u32 aQ = sb + O_QH + (u32)((warp * 16 + (lane & 15)) * RSQK
                                     + ((lane >> 4) << 4));
    const u32 rowB = (u32)((((lane >> 4) & 1) << 3) + (lane & 7));
    const u32 colB = (u32)(((lane >> 3) & 1) << 4);

    float accO[16][4];
#pragma unroll
    for (int nt = 0; nt < 16; nt++)
#pragma unroll
        for (int q = 0; q < 4; q++) accO[nt][q] = 0.f;
    float rs0 = 0.f, rs1 = 0.f;

#pragma unroll 1
    for (int jt = 0; jt < NJS; jt++) {
        const int cur = jt & 1;
        const u32 kB = sb + (cur ? O_K1 : O_K0) + rowB * RSQK + colB;
        const u32 vB = sb + (cur ? O_V1 : O_V0) + rowB * RSV + colB;

        // ---- S = q . k^T  (M=16/warp, N=64, K=128) ----
        float accS[8][4];
#pragma unroll
        for (int nt = 0; nt < 8; nt++)
#pragma unroll
            for (int q = 0; q < 4; q++) accS[nt][q] = 0.f;
#pragma unroll
        for (int ks = 0; ks < 8; ks++) {
            u32 ah[4], al[4];
            ldm4(ah, aQ + ks * 32);
            ldm4(al, aQ + ks * 32 + TQ);
#pragma unroll
            for (int np = 0; np < 4; np++) {
                u32 bh[4], bl[4];
                ldm4(bh, kB + np * (16 * RSQK) + ks * 32);
                ldm4(bl, kB + np * (16 * RSQK) + ks * 32 + TK);
                mma_bf16(accS[2 * np],     ah, bh);
                mma_bf16(accS[2 * np],     al, bh);
                mma_bf16(accS[2 * np],     ah, bl);
                mma_bf16(accS[2 * np + 1], ah, bh + 2);
                mma_bf16(accS[2 * np + 1], al, bh + 2);
                mma_bf16(accS[2 * np + 1], ah, bl + 2);
            }
        }

        // ---- p = exp(S) repacked into A fragments (register-only) ----
        u32 pa[4][4], pb[4][4];
#pragma unroll
        for (int ks = 0; ks < 4; ks++) {
#pragma unroll
            for (int h = 0; h < 2; h++) {
                const int nt = 2 * ks + h;
                float e0 = __expf(accS[nt][0]);
                float e1 = __expf(accS[nt][1]);
                float e2 = __expf(accS[nt][2]);
                float e3 = __expf(accS[nt][3]);
                rs0 += e0 + e1; rs1 += e2 + e3;
                __nv_bfloat16 h0 = __float2bfloat16(e0), h1 = __float2bfloat16(e1);
                __nv_bfloat16 h2 = __float2bfloat16(e2), h3 = __float2bfloat16(e3);
                pa[ks][2 * h]     = (u32)__bfloat16_as_ushort(h0)
                                  | ((u32)__bfloat16_as_ushort(h1) << 16);
                pa[ks][2 * h + 1] = (u32)__bfloat16_as_ushort(h2)
                                  | ((u32)__bfloat16_as_ushort(h3) << 16);
                pb[ks][2 * h]     = packbf2(e0 - __bfloat162float(h0),
                                            e1 - __bfloat162float(h1));
                pb[ks][2 * h + 1] = packbf2(e2 - __bfloat162float(h2),
                                            e3 - __bfloat162float(h3));
            }
        }

        // ---- out += p . v^T  (M=16, N=128 c, K=64 j) ----
#pragma unroll
        for (int ks = 0; ks < 4; ks++) {
#pragma unroll
            for (int np = 0; np < 8; np++) {
                u32 wh[4], wl[4];
                ldm4(wh, vB + np * (16 * RSV) + ks * 32);
                ldm4(wl, vB + np * (16 * RSV) + ks * 32 + TV);
                mma_bf16(accO[2 * np],     pa[ks], wh);
                mma_bf16(accO[2 * np],     pb[ks], wh);
                mma_bf16(accO[2 * np],     pa[ks], wl);
                mma_bf16(accO[2 * np + 1], pa[ks], wh + 2);
                mma_bf16(accO[2 * np + 1], pb[ks], wh + 2);
                mma_bf16(accO[2 * np + 1], pa[ks], wl + 2);
            }
        }

        // ---- iteration boundary: refill buffer `cur` with jt+2 ----
        __syncthreads();                 // all warps done with buffer `cur`
        if (jt + 2 < NJS) {
            const u32 kD = sb + (cur ? O_K1 : O_K0);
            const u32 vD = sb + (cur ? O_V1 : O_V0);
            cp_k(kD,      kh + (size_t)(jt + 2) * 64 * 256, tid);
            cp_k(kD + TK, kl + (size_t)(jt + 2) * 64 * 256, tid);
            cp_v(vD,      vh + (size_t)(jt + 2) * 128, tid);
            cp_v(vD + TV, vl + (size_t)(jt + 2) * 128, tid);
            CPCOMMIT();
            CPWAIT(1);                   // jt+1's group (a full iteration old)
        } else {
            CPWAIT(0);
        }
        __syncthreads();
    }

    // ---- rowsum reduce (quad shuffle) -> smem ----
    float* rssm = (float*)(sm + O_RS);
    rs0 += __shfl_xor_sync(0xffffffffu, rs0, 1);
    rs0 += __shfl_xor_sync(0xffffffffu, rs0, 2);
    rs1 += __shfl_xor_sync(0xffffffffu, rs1, 1);
    rs1 += __shfl_xor_sync(0xffffffffu, rs1, 2);
    if ((lane & 3) == 0) {
        rssm[warp * 16 + (lane >> 2)]     = rs0;
        rssm[warp * 16 + 8 + (lane >> 2)] = rs1;
    }

    // ---- transpose accO (Dt[i][c]) -> trans[c][i] in smem (q region) ----
    float* trans = (float*)sm;           // 128 x 132 floats = 67584 B
    __syncthreads();
    {
        const int r = lane >> 2, c0 = 2 * (lane & 3);
        const int iA = warp * 16 + r, iB = iA + 8;
#pragma unroll
        for (int nt = 0; nt < 16; nt++) {
            const int c = nt * 8 + c0;
            trans[c * 132 + iA]       = accO[nt][0];
            trans[(c + 1) * 132 + iA] = accO[nt][1];
            trans[c * 132 + iB]       = accO[nt][2];
            trans[(c + 1) * 132 + iB] = accO[nt][3];
        }
    }
    __syncthreads();

    // ---- coalesced epilogue: /rowsum *gamma + x*se ----
    const float gam = gamma[0];
    float4 rsv = *(float4*)&rssm[lane * 4];
    const float4 ri = make_float4(1.f / rsv.x, 1.f / rsv.y, 1.f / rsv.z, 1.f / rsv.w);
#pragma unroll
    for (int r = 0; r < 16; r++) {
        const int c = warp * 16 + r;
        const float sec = g_se[b * CH + c];
        const size_t base = (size_t)(b * CH + c) * NPIX + i0 + lane * 4;
        float4 tv = *(float4*)&trans[c * 132 + lane * 4];
        float4 xv = *(const float4*)&x[base];
        float4 o;
        o.x = gam * (tv.x * ri.x) + xv.x * sec;
        o.y = gam * (tv.y * ri.y) + xv.y * sec;
        o.z = gam * (tv.z * ri.z) + xv.z * sec;
        o.w = gam * (tv.w * ri.w) + xv.w * sec;
        *(float4*)&outp[base] = o;
    }
}

// =============================================================================
extern "C" void kernel_launch(void* const* d_in, const int* in_sizes, int n_in,
                              void* d_out, int out_size)
{
    const float* x     = (const float*)d_in[0];
    const float* Wq    = (const float*)d_in[1];
    const float* bq    = (const float*)d_in[2];
    const float* Wk    = (const float*)d_in[3];
    const float* bk    = (const float*)d_in[4];
    const float* Wv    = (const float*)d_in[5];
    const float* bv    = (const float*)d_in[6];
    const float* w1    = (const float*)d_in[7];
    const float* w2    = (const float*)d_in[8];
    const float* gamma = (const float*)d_in[9];
    float* out = (float*)d_out;

    cudaFuncSetAttribute(fused_attn, cudaFuncAttributeMaxDynamicSharedMemorySize,
                         SMEM_F);

    qkv_kernel<<<dim3(NPIX / 64, BATCH, 3), 256>>>(x, Wq, bq, Wk, bk, Wv, bv);
    mean_kernel<<<BATCH * CH, 256>>>(x);
    se_kernel<<<1, 128>>>(w1, w2);
    fused_attn<<<dim3(NIT, BATCH), 256, SMEM_F>>>(x, gamma, out);
}